// round 16
// baseline (speedup 1.0000x reference)
#include <cuda_runtime.h>

#define HH 1024
#define WW 2048
#define HWTOT (HH * WW)
#define NTILE 1024
#define GRIDP 296

#define EX_BYTES   (2 * 10 * 260 * 4)    // 20800, double-buffered exchange
#define SBUF_BYTES (10 * 256 * 16)       // 40960 per stream buffer
#define DSM_TOTAL  (EX_BYTES + 2 * SBUF_BYTES)

#define FLUXC    0.87890625f              // 300*H_STEP
#define F_COEF   0.002574920654296875f    // FLUX*H_STEP
#define WC0V_F ((float)(651.83 * 202.412 * 0.001 / 2.0))

// Cubic Taylor of K(tc) about tc=0 (t=273.15K)
#define K_C0 (-5.517e-4f)
#define K_C1 ( 4.242e-5f)
#define K_C2 ( 1.399e-6f)
#define K_C3 ( 2.569e-8f)

#define CXP_MASK ((1u<<4)|(1u<<9)|(1u<<10))
#define CXN_MASK ((1u<<6)|(1u<<8)|(1u<<11))
#define CYP_MASK ((1u<<7)|(1u<<8)|(1u<<9))
#define CYN_MASK ((1u<<5)|(1u<<10)|(1u<<11))

#define CP16(dst, src) asm volatile("cp.async.cg.shared.global [%0], [%1], 16;" :: "r"(dst), "l"(src))
#define CP_COMMIT()    asm volatile("cp.async.commit_group;" ::: "memory")
#define CP_WAIT0()     asm volatile("cp.async.wait_group 0;" ::: "memory")

__device__ float        g_sums[4] = {0.f, 0.f, 0.f, 0.f};
__device__ unsigned int g_count   = 0;

__device__ __forceinline__ int b_val(int raw, int r, int c) {
    if (r == 0 || r == HH - 1) return 3;
    if (c == WW - 1) return 3;
    if (c == 1) return 0;
    if ((r == 1 || r == HH - 2) && c >= 2) return 0;
    return raw;
}

// store 8 values per thread into p[base..base+7]; (p+base) is 4 mod 16,
// so shift the window by 3: two aligned STG.128 for lanes 0..30.
__device__ __forceinline__ void store8(float* __restrict__ p, int base, int lane,
                                       const float* v) {
    const float s0 = __shfl_down_sync(0xffffffffu, v[0], 1);
    const float s1 = __shfl_down_sync(0xffffffffu, v[1], 1);
    const float s2 = __shfl_down_sync(0xffffffffu, v[2], 1);
    *(float4*)(p + base + 3) = make_float4(v[3], v[4], v[5], v[6]);
    if (lane == 31) {
        p[base + 7] = v[7];
    } else {
        *(float4*)(p + base + 7) = make_float4(v[7], s0, s1, s2);
    }
    if (lane == 0) { p[base] = v[0]; p[base + 1] = v[1]; p[base + 2] = v[2]; }
}

// pipelined stencil register set for one tile
struct St {
    int4   bA, bB;   float4 hA, hB;    // center braw / heat
    int4   xbA, xbB; float4 xhA, xhB;  // halo row (warp0: up, warp7: down)
    int    lB, rB;   float  lS, rS;    // corner scalars (lane 0 / 31)
};

__device__ __forceinline__ void load_stencil(St& s, const int* __restrict__ braw,
                                             const float* __restrict__ heat,
                                             int t, int warp, int lane)
{
    const int tile_c = t & 7, tile_r = t >> 3;
    const int r    = tile_r * 8 + warp;
    const int cb   = tile_c * 256 + lane * 8;
    const int base = r * WW + cb;

    s.bA = *(const int4*)(braw + base);
    s.bB = *(const int4*)(braw + base + 4);
    s.hA = *(const float4*)(heat + base);
    s.hB = *(const float4*)(heat + base + 4);

    s.xbA = make_int4(1, 1, 1, 1); s.xbB = make_int4(1, 1, 1, 1);
    s.xhA = make_float4(0.f, 0.f, 0.f, 0.f); s.xhB = s.xhA;
    if (warp == 0) {
        if (r > 0) {
            s.xbA = *(const int4*)(braw + base - WW);
            s.xbB = *(const int4*)(braw + base - WW + 4);
            s.xhA = *(const float4*)(heat + base - WW);
            s.xhB = *(const float4*)(heat + base - WW + 4);
        }
    } else if (warp == 7) {
        if (r < HH - 1) {
            s.xbA = *(const int4*)(braw + base + WW);
            s.xbB = *(const int4*)(braw + base + WW + 4);
            s.xhA = *(const float4*)(heat + base + WW);
            s.xhB = *(const float4*)(heat + base + WW + 4);
        }
    }

    s.lB = 1; s.rB = 1; s.lS = 0.f; s.rS = 0.f;
    if (lane == 0 && cb > 0)       { s.lB = braw[base - 1]; s.lS = heat[base - 1]; }
    if (lane == 31 && cb + 8 < WW) { s.rB = braw[base + 8]; s.rS = heat[base + 8]; }
}

// issue cp.async for tile t's 10 stream vectors into stream buffer `buf`
__device__ __forceinline__ void issue_streams(
    unsigned sb_base, int buf, int t, int warp, int lane,
    const int* __restrict__ layout, const float* __restrict__ heat_ini,
    const float* __restrict__ wc,   const float* __restrict__ flow)
{
    const int tile_c = t & 7, tile_r = t >> 3;
    const int r    = tile_r * 8 + warp;
    const int cb   = tile_c * 256 + lane * 8;
    const int base = r * WW + cb;
    const unsigned sb = sb_base + (unsigned)buf * SBUF_BYTES + (unsigned)threadIdx.x * 16u;

    CP16(sb + 0u * 4096u, layout + base);
    CP16(sb + 1u * 4096u, layout + base + 4);
    CP16(sb + 2u * 4096u, heat_ini + base);
    CP16(sb + 3u * 4096u, heat_ini + base + 4);
    CP16(sb + 4u * 4096u, wc + base);
    CP16(sb + 5u * 4096u, wc + base + 4);
    CP16(sb + 6u * 4096u, flow + base);
    CP16(sb + 7u * 4096u, flow + base + 4);
    CP16(sb + 8u * 4096u, flow + HWTOT + base);
    CP16(sb + 9u * 4096u, flow + HWTOT + base + 4);
    CP_COMMIT();
}

template<bool FAST>
__device__ __forceinline__ void iter_body(
    const St& cur, St& nxt, int t, int tn,
    const int* __restrict__ layout, const float* __restrict__ heat_ini,
    const float* __restrict__ wc,   const float* __restrict__ heat,
    const float* __restrict__ flow, float* __restrict__ out,
    int warp, int lane, float (*sm)[260], char* dynsm, unsigned sb_base, int buf,
    float& d0, float& d1, float& d2, float& d3)
{
    const int* __restrict__ braw = layout + HWTOT;
    const int tile_c = t & 7, tile_r = t >> 3;
    const int r    = tile_r * 8 + warp;
    const int cb   = tile_c * 256 + lane * 8;
    const int base = r * WW + cb;

    // ---- mask + STS previously-loaded stencil (no memory wait) ----
    const int   brs[8] = {cur.bA.x, cur.bA.y, cur.bA.z, cur.bA.w,
                          cur.bB.x, cur.bB.y, cur.bB.z, cur.bB.w};
    const float hsv[8] = {cur.hA.x, cur.hA.y, cur.hA.z, cur.hA.w,
                          cur.hB.x, cur.hB.y, cur.hB.z, cur.hB.w};
    int   bs[8];
    float hb[8];
#pragma unroll
    for (int j = 0; j < 8; j++) {
        bs[j] = FAST ? brs[j] : b_val(brs[j], r, cb + j);
        hb[j] = (bs[j] == 1) ? 0.f : hsv[j];
    }
    *(float4*)&sm[warp + 1][lane * 8]     = make_float4(hb[0], hb[1], hb[2], hb[3]);
    *(float4*)&sm[warp + 1][lane * 8 + 4] = make_float4(hb[4], hb[5], hb[6], hb[7]);

    if (warp == 0 || warp == 7) {
        const int rr  = (warp == 0) ? (r - 1) : (r + 1);
        const int row = (warp == 0) ? 0 : 9;
        const int xb[8] = {cur.xbA.x, cur.xbA.y, cur.xbA.z, cur.xbA.w,
                           cur.xbB.x, cur.xbB.y, cur.xbB.z, cur.xbB.w};
        const float xh[8] = {cur.xhA.x, cur.xhA.y, cur.xhA.z, cur.xhA.w,
                             cur.xhB.x, cur.xhB.y, cur.xhB.z, cur.xhB.w};
        float m[8];
#pragma unroll
        for (int j = 0; j < 8; j++) {
            const int bb2 = FAST ? xb[j] : b_val(xb[j], rr, cb + j);
            m[j] = (bb2 == 1) ? 0.f : xh[j];
        }
        *(float4*)&sm[row][lane * 8]     = make_float4(m[0], m[1], m[2], m[3]);
        *(float4*)&sm[row][lane * 8 + 4] = make_float4(m[4], m[5], m[6], m[7]);
    }
    __syncthreads();

    // ---- consume staged streams for tile t (LDS from smem, ~29 cyc) ----
    CP_WAIT0();
    char* sp = dynsm + EX_BYTES + (size_t)buf * SBUF_BYTES + (size_t)threadIdx.x * 16;
    const int4   gA  = *(const int4*)  (sp + 0 * 4096);
    const int4   gB  = *(const int4*)  (sp + 1 * 4096);
    const float4 hiA = *(const float4*)(sp + 2 * 4096);
    const float4 hiB = *(const float4*)(sp + 3 * 4096);
    const float4 wA  = *(const float4*)(sp + 4 * 4096);
    const float4 wB  = *(const float4*)(sp + 5 * 4096);
    const float4 uA  = *(const float4*)(sp + 6 * 4096);
    const float4 uB  = *(const float4*)(sp + 7 * 4096);
    const float4 vA  = *(const float4*)(sp + 8 * 4096);
    const float4 vB  = *(const float4*)(sp + 9 * 4096);

    // ---- prefetch next tile: streams via cp.async (no regs), stencil via regs ----
    if (tn < NTILE) {
        issue_streams(sb_base, buf ^ 1, tn, warp, lane, layout, heat_ini, wc, flow);
        load_stencil(nxt, braw, heat, tn, warp, lane);
    }

    // ---- compute tile t ----
    const float4 upA = *(const float4*)&sm[warp][lane * 8];
    const float4 upB = *(const float4*)&sm[warp][lane * 8 + 4];
    const float4 dnA = *(const float4*)&sm[warp + 2][lane * 8];
    const float4 dnB = *(const float4*)&sm[warp + 2][lane * 8 + 4];
    const float hbu[8] = {upA.x, upA.y, upA.z, upA.w, upB.x, upB.y, upB.z, upB.w};
    const float hbd[8] = {dnA.x, dnA.y, dnA.z, dnA.w, dnB.x, dnB.y, dnB.z, dnB.w};

    float leftN  = __shfl_up_sync(0xffffffffu, hb[7], 1);
    float rightN = __shfl_down_sync(0xffffffffu, hb[0], 1);
    if (lane == 0) {
        const int bl = FAST ? cur.lB : ((cb > 0) ? b_val(cur.lB, r, cb - 1) : 1);
        leftN = (bl == 1) ? 0.f : cur.lS;
    }
    if (lane == 31) {
        const int br_ = FAST ? cur.rB : ((cb + 8 < WW) ? b_val(cur.rB, r, cb + 8) : 1);
        rightN = (br_ == 1) ? 0.f : cur.rS;
    }

    float hbx[10];
    hbx[0] = leftN;
#pragma unroll
    for (int j = 0; j < 8; j++) hbx[j + 1] = hb[j];
    hbx[9] = rightN;

    const int   ggs[8] = {gA.x, gA.y, gA.z, gA.w, gB.x, gB.y, gB.z, gB.w};
    const float his[8] = {hiA.x, hiA.y, hiA.z, hiA.w, hiB.x, hiB.y, hiB.z, hiB.w};
    const float ws[8]  = {wA.x, wA.y, wA.z, wA.w, wB.x, wB.y, wB.z, wB.w};
    const float us[8]  = {uA.x, uA.y, uA.z, uA.w, uB.x, uB.y, uB.z, uB.w};
    const float vs[8]  = {vA.x, vA.y, vA.z, vA.w, vB.x, vB.y, vB.z, vB.w};

    const bool has_y    = FAST || ((r > 0) && (r < HH - 1));
    const bool edge_row = FAST ? false : ((r == 0) || (r == HH - 1));

    float eqv[8];
#pragma unroll
    for (int j = 0; j < 8; j++) {
        const int c = cb + j;
        const int b = bs[j];

        float dx = 0.5f * (hbx[j + 2] - hbx[j]);
        if (!FAST && (c == 0 || c == WW - 1)) dx = 0.f;
        const float dy = has_y ? 0.5f * (hbd[j] - hbu[j]) : 0.f;

        const float geom = edge_row ? 1.f : (float)ggs[j];
        const float f    = fabsf(geom - 1.f) * F_COEF;

        const float ad = fmaf(-0.001f, fmaf(us[j], dx, vs[j] * dy), his[j]);

        const float wcm = (b > 3) ? 1.f : 0.f;
        d3 += ws[j] * wcm;

        const float tc = hb[j];
        const float K  = fmaf(fmaf(fmaf(K_C3, tc, K_C2), tc, K_C1), tc, K_C0);

        const unsigned bb = 1u << b;
        const float cxdx = ((bb & CXP_MASK) ? dx : 0.f) - ((bb & CXN_MASK) ? dx : 0.f);
        const float cydy = ((bb & CYP_MASK) ? dy : 0.f) - ((bb & CYN_MASK) ? dy : 0.f);
        const float e    = (b >= 4) ? 1.f : 0.f;

        float A;
        if (b == 1) A = -f;
        else        A = fmaf(FLUXC, cxdx + cydy, ad) + fmaf(e, WC0V_F, -f);

        const float Aw = wcm * (WC0V_F - ws[j]);

        d0 += fmaf(A, A, Aw * Aw);
        const float tmp = fmaf(0.001f * e, A, Aw);
        d1 = fmaf(-2.f * K, tmp, d1);
        const float K2 = K * K;
        d2 += fmaf(1e-6f * e, K2, K2);

        eqv[j] = (float)((b == 1) ? 0 : b);
    }

    store8(out + 1,         base, lane, hb);
    store8(out + 1 + HWTOT, base, lane, eqv);
}

__global__ __launch_bounds__(256, 2) void energy_evp_main(
    const int*   __restrict__ layout,
    const float* __restrict__ heat_ini,
    const float* __restrict__ wc,
    const float* __restrict__ heat,
    const float* __restrict__ flow,
    float*       __restrict__ out)
{
    extern __shared__ char dynsm[];

    const int warp = threadIdx.x >> 5;
    const int lane = threadIdx.x & 31;
    const int* __restrict__ braw = layout + HWTOT;
    const unsigned sb_base = (unsigned)__cvta_generic_to_shared(dynsm) + EX_BYTES;

    float d0 = 0.f, d1 = 0.f, d2 = 0.f, d3 = 0.f;

    St cur, nxt;
    int t = blockIdx.x;
    issue_streams(sb_base, 0, t, warp, lane, layout, heat_ini, wc, flow);
    load_stencil(cur, braw, heat, t, warp, lane);

    int buf = 0;
    for (; t < NTILE; t += GRIDP, buf ^= 1) {
        const int tn = t + GRIDP;
        const int tile_c = t & 7, tile_r = t >> 3;
        float (*ex)[260] = (float(*)[260])(dynsm + (size_t)buf * 10 * 260 * 4);
        const bool fast = (tile_r >= 1) && (tile_r <= 126) && (tile_c >= 1) && (tile_c <= 6);
        if (fast) iter_body<true >(cur, nxt, t, tn, layout, heat_ini, wc, heat, flow, out, warp, lane, ex, dynsm, sb_base, buf, d0, d1, d2, d3);
        else      iter_body<false>(cur, nxt, t, tn, layout, heat_ini, wc, heat, flow, out, warp, lane, ex, dynsm, sb_base, buf, d0, d1, d2, d3);
        cur = nxt;
    }

    // warp tree reduce (float)
#pragma unroll
    for (int o = 16; o > 0; o >>= 1) {
        d0 += __shfl_down_sync(0xffffffffu, d0, o);
        d1 += __shfl_down_sync(0xffffffffu, d1, o);
        d2 += __shfl_down_sync(0xffffffffu, d2, o);
        d3 += __shfl_down_sync(0xffffffffu, d3, o);
    }
    __shared__ float sh[8][4];
    const int tid = threadIdx.x;
    if (lane == 0) {
        sh[warp][0] = d0; sh[warp][1] = d1; sh[warp][2] = d2; sh[warp][3] = d3;
    }
    __syncthreads();

    if (tid == 0) {
        float s0 = 0.f, s1 = 0.f, s2 = 0.f, s3 = 0.f;
#pragma unroll
        for (int w = 0; w < 8; w++) {
            s0 += sh[w][0]; s1 += sh[w][1]; s2 += sh[w][2]; s3 += sh[w][3];
        }
        atomicAdd(&g_sums[0], s0);
        atomicAdd(&g_sums[1], s1);
        atomicAdd(&g_sums[2], s2);
        atomicAdd(&g_sums[3], s3);
        __threadfence();
        unsigned old = atomicAdd(&g_count, 1u);
        if (old == GRIDP - 1) {
            const float S0 = __ldcg(&g_sums[0]);
            const float S1 = __ldcg(&g_sums[1]);
            const float S2 = __ldcg(&g_sums[2]);
            const float S3 = __ldcg(&g_sums[3]);
            const float invN = 1.f / (float)HWTOT;
            const float mean = S3 * invN;
            const float C3   = sqrtf(mean / WC0V_F);
            const float loss = (S0 + S1 * C3 + S2 * C3 * C3) * invN;
            out[0] = loss;
            g_sums[0] = 0.f; g_sums[1] = 0.f; g_sums[2] = 0.f; g_sums[3] = 0.f;
            __threadfence();
            g_count = 0;
        }
    }
}

extern "C" void kernel_launch(void* const* d_in, const int* in_sizes, int n_in,
                              void* d_out, int out_size) {
    const int*   layout   = (const int*)d_in[0];
    const float* heat_ini = (const float*)d_in[1];
    const float* wc       = (const float*)d_in[2];
    const float* heat     = (const float*)d_in[3];
    const float* flow     = (const float*)d_in[4];
    float* out = (float*)d_out;

    cudaFuncSetAttribute(energy_evp_main,
                         cudaFuncAttributeMaxDynamicSharedMemorySize, DSM_TOTAL);
    energy_evp_main<<<GRIDP, 256, DSM_TOTAL>>>(layout, heat_ini, wc, heat, flow, out);
}

// round 17
// speedup vs baseline: 1.3631x; 1.3631x over previous
#include <cuda_runtime.h>

#define HH 1024
#define WW 2048
#define HWTOT (HH * WW)
#define NTILE 1024
#define GRIDP 296

#define FLUXC    0.87890625f              // 300*H_STEP
#define F_COEF   0.002574920654296875f    // FLUX*H_STEP
#define WC0V_F ((float)(651.83 * 202.412 * 0.001 / 2.0))

// Cubic Taylor of K(tc) about tc=0 (t=273.15K)
#define K_C0 (-5.517e-4f)
#define K_C1 ( 4.242e-5f)
#define K_C2 ( 1.399e-6f)
#define K_C3 ( 2.569e-8f)

#define CXP_MASK ((1u<<4)|(1u<<9)|(1u<<10))
#define CXN_MASK ((1u<<6)|(1u<<8)|(1u<<11))
#define CYP_MASK ((1u<<7)|(1u<<8)|(1u<<9))
#define CYN_MASK ((1u<<5)|(1u<<10)|(1u<<11))

__device__ float        g_sums[4] = {0.f, 0.f, 0.f, 0.f};
__device__ unsigned int g_count   = 0;

__device__ __forceinline__ int b_val(int raw, int r, int c) {
    if (r == 0 || r == HH - 1) return 3;
    if (c == WW - 1) return 3;
    if (c == 1) return 0;
    if ((r == 1 || r == HH - 2) && c >= 2) return 0;
    return raw;
}

// store 8 values per thread into p[base..base+7]; (p+base) is 4 mod 16,
// so shift the window by 3: two aligned STG.128 (evict-first) for lanes 0..30.
__device__ __forceinline__ void store8(float* __restrict__ p, int base, int lane,
                                       const float* v) {
    const float s0 = __shfl_down_sync(0xffffffffu, v[0], 1);
    const float s1 = __shfl_down_sync(0xffffffffu, v[1], 1);
    const float s2 = __shfl_down_sync(0xffffffffu, v[2], 1);
    __stcs((float4*)(p + base + 3), make_float4(v[3], v[4], v[5], v[6]));
    if (lane == 31) {
        __stcs(p + base + 7, v[7]);
    } else {
        __stcs((float4*)(p + base + 7), make_float4(v[7], s0, s1, s2));
    }
    if (lane == 0) {
        __stcs(p + base, v[0]);
        __stcs(p + base + 1, v[1]);
        __stcs(p + base + 2, v[2]);
    }
}

// pipelined stencil register set for one tile
struct St {
    int4   bA, bB;   float4 hA, hB;    // center braw / heat
    int4   xbA, xbB; float4 xhA, xhB;  // halo row (warp0: up, warp7: down)
    int    lB, rB;   float  lS, rS;    // corner scalars (lane 0 / 31)
};

__device__ __forceinline__ void load_stencil(St& s, const int* __restrict__ braw,
                                             const float* __restrict__ heat,
                                             int t, int warp, int lane)
{
    const int tile_c = t & 7, tile_r = t >> 3;
    const int r    = tile_r * 8 + warp;
    const int cb   = tile_c * 256 + lane * 8;
    const int base = r * WW + cb;

    s.bA = *(const int4*)(braw + base);
    s.bB = *(const int4*)(braw + base + 4);
    s.hA = *(const float4*)(heat + base);
    s.hB = *(const float4*)(heat + base + 4);

    s.xbA = make_int4(1, 1, 1, 1); s.xbB = make_int4(1, 1, 1, 1);
    s.xhA = make_float4(0.f, 0.f, 0.f, 0.f); s.xhB = s.xhA;
    if (warp == 0) {
        if (r > 0) {
            s.xbA = *(const int4*)(braw + base - WW);
            s.xbB = *(const int4*)(braw + base - WW + 4);
            s.xhA = *(const float4*)(heat + base - WW);
            s.xhB = *(const float4*)(heat + base - WW + 4);
        }
    } else if (warp == 7) {
        if (r < HH - 1) {
            s.xbA = *(const int4*)(braw + base + WW);
            s.xbB = *(const int4*)(braw + base + WW + 4);
            s.xhA = *(const float4*)(heat + base + WW);
            s.xhB = *(const float4*)(heat + base + WW + 4);
        }
    }

    s.lB = 1; s.rB = 1; s.lS = 0.f; s.rS = 0.f;
    if (lane == 0 && cb > 0)       { s.lB = braw[base - 1]; s.lS = heat[base - 1]; }
    if (lane == 31 && cb + 8 < WW) { s.rB = braw[base + 8]; s.rS = heat[base + 8]; }
}

template<bool FAST>
__device__ __forceinline__ void iter_body(
    const St& cur, St& nxt, int t, int tn,
    const int* __restrict__ layout, const float* __restrict__ heat_ini,
    const float* __restrict__ wc,   const float* __restrict__ heat,
    const float* __restrict__ flow, float* __restrict__ out,
    int warp, int lane, float (*sm)[260],
    float& d0, float& d1, float& d2, float& d3)
{
    const int* __restrict__ braw = layout + HWTOT;
    const int tile_c = t & 7, tile_r = t >> 3;
    const int r    = tile_r * 8 + warp;
    const int cb   = tile_c * 256 + lane * 8;
    const int base = r * WW + cb;

    // ---- mask + STS previously-loaded stencil (no memory wait) ----
    const int   brs[8] = {cur.bA.x, cur.bA.y, cur.bA.z, cur.bA.w,
                          cur.bB.x, cur.bB.y, cur.bB.z, cur.bB.w};
    const float hsv[8] = {cur.hA.x, cur.hA.y, cur.hA.z, cur.hA.w,
                          cur.hB.x, cur.hB.y, cur.hB.z, cur.hB.w};
    int   bs[8];
    float hb[8];
#pragma unroll
    for (int j = 0; j < 8; j++) {
        bs[j] = FAST ? brs[j] : b_val(brs[j], r, cb + j);
        hb[j] = (bs[j] == 1) ? 0.f : hsv[j];
    }
    *(float4*)&sm[warp + 1][lane * 8]     = make_float4(hb[0], hb[1], hb[2], hb[3]);
    *(float4*)&sm[warp + 1][lane * 8 + 4] = make_float4(hb[4], hb[5], hb[6], hb[7]);

    if (warp == 0 || warp == 7) {
        const int rr  = (warp == 0) ? (r - 1) : (r + 1);
        const int row = (warp == 0) ? 0 : 9;
        const int xb[8] = {cur.xbA.x, cur.xbA.y, cur.xbA.z, cur.xbA.w,
                           cur.xbB.x, cur.xbB.y, cur.xbB.z, cur.xbB.w};
        const float xh[8] = {cur.xhA.x, cur.xhA.y, cur.xhA.z, cur.xhA.w,
                             cur.xhB.x, cur.xhB.y, cur.xhB.z, cur.xhB.w};
        float m[8];
#pragma unroll
        for (int j = 0; j < 8; j++) {
            const int bb2 = FAST ? xb[j] : b_val(xb[j], rr, cb + j);
            m[j] = (bb2 == 1) ? 0.f : xh[j];
        }
        *(float4*)&sm[row][lane * 8]     = make_float4(m[0], m[1], m[2], m[3]);
        *(float4*)&sm[row][lane * 8 + 4] = make_float4(m[4], m[5], m[6], m[7]);
    }
    __syncthreads();

    // ---- stream loads for tile t (consumed mid-compute) ----
    const int4   gA  = *(const int4*)(layout + base);
    const int4   gB  = *(const int4*)(layout + base + 4);
    const float4 hiA = *(const float4*)(heat_ini + base);
    const float4 hiB = *(const float4*)(heat_ini + base + 4);
    const float4 wA  = *(const float4*)(wc + base);
    const float4 wB  = *(const float4*)(wc + base + 4);
    const float4 uA  = *(const float4*)(flow + base);
    const float4 uB  = *(const float4*)(flow + base + 4);
    const float4 vA  = *(const float4*)(flow + HWTOT + base);
    const float4 vB  = *(const float4*)(flow + HWTOT + base + 4);

    // ---- pipeline: next tile's stencil (consumed next iteration) ----
    if (tn < NTILE) load_stencil(nxt, braw, heat, tn, warp, lane);

    // ---- compute tile t ----
    const float4 upA = *(const float4*)&sm[warp][lane * 8];
    const float4 upB = *(const float4*)&sm[warp][lane * 8 + 4];
    const float4 dnA = *(const float4*)&sm[warp + 2][lane * 8];
    const float4 dnB = *(const float4*)&sm[warp + 2][lane * 8 + 4];
    const float hbu[8] = {upA.x, upA.y, upA.z, upA.w, upB.x, upB.y, upB.z, upB.w};
    const float hbd[8] = {dnA.x, dnA.y, dnA.z, dnA.w, dnB.x, dnB.y, dnB.z, dnB.w};

    float leftN  = __shfl_up_sync(0xffffffffu, hb[7], 1);
    float rightN = __shfl_down_sync(0xffffffffu, hb[0], 1);
    if (lane == 0) {
        const int bl = FAST ? cur.lB : ((cb > 0) ? b_val(cur.lB, r, cb - 1) : 1);
        leftN = (bl == 1) ? 0.f : cur.lS;
    }
    if (lane == 31) {
        const int br_ = FAST ? cur.rB : ((cb + 8 < WW) ? b_val(cur.rB, r, cb + 8) : 1);
        rightN = (br_ == 1) ? 0.f : cur.rS;
    }

    float hbx[10];
    hbx[0] = leftN;
#pragma unroll
    for (int j = 0; j < 8; j++) hbx[j + 1] = hb[j];
    hbx[9] = rightN;

    const int   ggs[8] = {gA.x, gA.y, gA.z, gA.w, gB.x, gB.y, gB.z, gB.w};
    const float his[8] = {hiA.x, hiA.y, hiA.z, hiA.w, hiB.x, hiB.y, hiB.z, hiB.w};
    const float ws[8]  = {wA.x, wA.y, wA.z, wA.w, wB.x, wB.y, wB.z, wB.w};
    const float us[8]  = {uA.x, uA.y, uA.z, uA.w, uB.x, uB.y, uB.z, uB.w};
    const float vs[8]  = {vA.x, vA.y, vA.z, vA.w, vB.x, vB.y, vB.z, vB.w};

    const bool has_y    = FAST || ((r > 0) && (r < HH - 1));
    const bool edge_row = FAST ? false : ((r == 0) || (r == HH - 1));

    float eqv[8];
#pragma unroll
    for (int j = 0; j < 8; j++) {
        const int c = cb + j;
        const int b = bs[j];

        float dx = 0.5f * (hbx[j + 2] - hbx[j]);
        if (!FAST && (c == 0 || c == WW - 1)) dx = 0.f;
        const float dy = has_y ? 0.5f * (hbd[j] - hbu[j]) : 0.f;

        const float geom = edge_row ? 1.f : (float)ggs[j];
        const float f    = fabsf(geom - 1.f) * F_COEF;

        const float ad = fmaf(-0.001f, fmaf(us[j], dx, vs[j] * dy), his[j]);

        const float wcm = (b > 3) ? 1.f : 0.f;
        d3 += ws[j] * wcm;

        const float tc = hb[j];
        const float K  = fmaf(fmaf(fmaf(K_C3, tc, K_C2), tc, K_C1), tc, K_C0);

        const unsigned bb = 1u << b;
        const float cxdx = ((bb & CXP_MASK) ? dx : 0.f) - ((bb & CXN_MASK) ? dx : 0.f);
        const float cydy = ((bb & CYP_MASK) ? dy : 0.f) - ((bb & CYN_MASK) ? dy : 0.f);
        const float e    = (b >= 4) ? 1.f : 0.f;

        float A;
        if (b == 1) A = -f;
        else        A = fmaf(FLUXC, cxdx + cydy, ad) + fmaf(e, WC0V_F, -f);

        const float Aw = wcm * (WC0V_F - ws[j]);

        d0 += fmaf(A, A, Aw * Aw);
        const float tmp = fmaf(0.001f * e, A, Aw);
        d1 = fmaf(-2.f * K, tmp, d1);
        const float K2 = K * K;
        d2 += fmaf(1e-6f * e, K2, K2);

        eqv[j] = (float)((b == 1) ? 0 : b);
    }

    store8(out + 1,         base, lane, hb);
    store8(out + 1 + HWTOT, base, lane, eqv);
}

__global__ __launch_bounds__(256, 2) void energy_evp_main(
    const int*   __restrict__ layout,
    const float* __restrict__ heat_ini,
    const float* __restrict__ wc,
    const float* __restrict__ heat,
    const float* __restrict__ flow,
    float*       __restrict__ out)
{
    // double-buffered exchange: no trailing per-iteration barrier needed
    __shared__ float sm[2][10][260];

    const int warp = threadIdx.x >> 5;
    const int lane = threadIdx.x & 31;
    const int* __restrict__ braw = layout + HWTOT;

    float d0 = 0.f, d1 = 0.f, d2 = 0.f, d3 = 0.f;

    St cur, nxt;
    load_stencil(cur, braw, heat, blockIdx.x, warp, lane);

    int buf = 0;
    for (int t = blockIdx.x; t < NTILE; t += GRIDP, buf ^= 1) {
        const int tn = t + GRIDP;
        const int tile_c = t & 7, tile_r = t >> 3;
        const bool fast = (tile_r >= 1) && (tile_r <= 126) && (tile_c >= 1) && (tile_c <= 6);
        if (fast) iter_body<true >(cur, nxt, t, tn, layout, heat_ini, wc, heat, flow, out, warp, lane, sm[buf], d0, d1, d2, d3);
        else      iter_body<false>(cur, nxt, t, tn, layout, heat_ini, wc, heat, flow, out, warp, lane, sm[buf], d0, d1, d2, d3);
        cur = nxt;
    }

    // warp tree reduce (float)
#pragma unroll
    for (int o = 16; o > 0; o >>= 1) {
        d0 += __shfl_down_sync(0xffffffffu, d0, o);
        d1 += __shfl_down_sync(0xffffffffu, d1, o);
        d2 += __shfl_down_sync(0xffffffffu, d2, o);
        d3 += __shfl_down_sync(0xffffffffu, d3, o);
    }
    __shared__ float sh[8][4];
    const int tid = threadIdx.x;
    if (lane == 0) {
        sh[warp][0] = d0; sh[warp][1] = d1; sh[warp][2] = d2; sh[warp][3] = d3;
    }
    __syncthreads();

    if (tid == 0) {
        float s0 = 0.f, s1 = 0.f, s2 = 0.f, s3 = 0.f;
#pragma unroll
        for (int w = 0; w < 8; w++) {
            s0 += sh[w][0]; s1 += sh[w][1]; s2 += sh[w][2]; s3 += sh[w][3];
        }
        atomicAdd(&g_sums[0], s0);
        atomicAdd(&g_sums[1], s1);
        atomicAdd(&g_sums[2], s2);
        atomicAdd(&g_sums[3], s3);
        __threadfence();
        unsigned old = atomicAdd(&g_count, 1u);
        if (old == GRIDP - 1) {
            const float S0 = __ldcg(&g_sums[0]);
            const float S1 = __ldcg(&g_sums[1]);
            const float S2 = __ldcg(&g_sums[2]);
            const float S3 = __ldcg(&g_sums[3]);
            const float invN = 1.f / (float)HWTOT;
            const float mean = S3 * invN;
            const float C3   = sqrtf(mean / WC0V_F);
            const float loss = (S0 + S1 * C3 + S2 * C3 * C3) * invN;
            out[0] = loss;
            g_sums[0] = 0.f; g_sums[1] = 0.f; g_sums[2] = 0.f; g_sums[3] = 0.f;
            __threadfence();
            g_count = 0;
        }
    }
}

extern "C" void kernel_launch(void* const* d_in, const int* in_sizes, int n_in,
                              void* d_out, int out_size) {
    const int*   layout   = (const int*)d_in[0];
    const float* heat_ini = (const float*)d_in[1];
    const float* wc       = (const float*)d_in[2];
    const float* heat     = (const float*)d_in[3];
    const float* flow     = (const float*)d_in[4];
    float* out = (float*)d_out;

    energy_evp_main<<<GRIDP, 256>>>(layout, heat_ini, wc, heat, flow, out);
}